// round 1
// baseline (speedup 1.0000x reference)
#include <cuda_runtime.h>
#include <math.h>

#define Bz   2
#define Tt   1024
#define Dd   512
#define NHh  8
#define HDd  64
#define Ll   4
#define Ee   8
#define Hh   2048
#define NT   (Bz*Tt)   // 2048 tokens

// ---------------- scratch (device globals; no allocation allowed) ----------
__device__ float g_h   [NT*Dd];          // residual stream
__device__ float g_xn  [NT*Dd];          // normed activations
__device__ float g_qkv [NT*3*Dd];
__device__ float g_q   [NT*Dd];
__device__ float g_k   [NT*Dd];
__device__ float g_v   [NT*Dd];
__device__ float g_attn[NT*Dd];
__device__ float g_hbuf[(size_t)Ee*NT*Hh];   // expert/dense hidden (134MB)
__device__ float g_yslot[2*NT*Dd];           // per (token,slot) expert output
__device__ int   g_cnt [Ee];
__device__ int   g_tok [Ee*NT];              // packed token*2+slot
__device__ float g_wt  [Ee*NT];

// ---------------- rmsnorm ---------------------------------------------------
__global__ void rmsnorm_kernel(const float* __restrict__ in,
                               const float* __restrict__ w,
                               float* __restrict__ out) {
    int row = blockIdx.x;
    const float* x = in + (size_t)row*Dd;
    float s = 0.f;
    for (int j = threadIdx.x; j < Dd; j += 256) { float v = x[j]; s += v*v; }
    __shared__ float red[8];
    for (int o = 16; o; o >>= 1) s += __shfl_xor_sync(0xffffffffu, s, o);
    if ((threadIdx.x & 31) == 0) red[threadIdx.x >> 5] = s;
    __syncthreads();
    if (threadIdx.x < 8) {
        float v = red[threadIdx.x];
        for (int o = 4; o; o >>= 1) v += __shfl_xor_sync(0xffu, v, o);
        if (threadIdx.x == 0) red[0] = v;
    }
    __syncthreads();
    float rms = rsqrtf(red[0] / (float)Dd + 1e-5f);
    for (int j = threadIdx.x; j < Dd; j += 256)
        out[(size_t)row*Dd + j] = w[j] * x[j] * rms;
}

// ---------------- generic C = A @ W^T (+res) --------------------------------
// A: [N,K], W: [M,K] row-major. Tile 64x64, K-step 16, 256 threads, 4x4 micro.
__global__ void gemm_nt_kernel(const float* __restrict__ A,
                               const float* __restrict__ W,
                               float* __restrict__ C,
                               const float* __restrict__ Res,
                               int M, int K) {
    __shared__ float As[64][17];
    __shared__ float Ws[64][17];
    int t  = threadIdx.x;
    int tx = t & 15, ty = t >> 4;
    int rb = blockIdx.y * 64, cb = blockIdx.x * 64;
    int lr = t >> 2, lk = (t & 3) << 2;
    float acc[4][4] = {};
    for (int k0 = 0; k0 < K; k0 += 16) {
        float4 av = *(const float4*)(A + (size_t)(rb + lr)*K + k0 + lk);
        float4 wv = *(const float4*)(W + (size_t)(cb + lr)*K + k0 + lk);
        As[lr][lk+0]=av.x; As[lr][lk+1]=av.y; As[lr][lk+2]=av.z; As[lr][lk+3]=av.w;
        Ws[lr][lk+0]=wv.x; Ws[lr][lk+1]=wv.y; Ws[lr][lk+2]=wv.z; Ws[lr][lk+3]=wv.w;
        __syncthreads();
#pragma unroll
        for (int kk = 0; kk < 16; kk++) {
            float a[4], b[4];
#pragma unroll
            for (int i = 0; i < 4; i++) a[i] = As[ty*4+i][kk];
#pragma unroll
            for (int j = 0; j < 4; j++) b[j] = Ws[tx*4+j][kk];
#pragma unroll
            for (int i = 0; i < 4; i++)
#pragma unroll
                for (int j = 0; j < 4; j++) acc[i][j] += a[i]*b[j];
        }
        __syncthreads();
    }
#pragma unroll
    for (int i = 0; i < 4; i++)
#pragma unroll
        for (int j = 0; j < 4; j++) {
            size_t idx = (size_t)(rb + ty*4 + i)*M + cb + tx*4 + j;
            float v = acc[i][j];
            if (Res) v += Res[idx];
            C[idx] = v;
        }
}

// ---------------- qkv split + RoPE ------------------------------------------
__global__ void split_rope_kernel(const float* __restrict__ qkv,
                                  float* __restrict__ Q,
                                  float* __restrict__ K,
                                  float* __restrict__ V) {
    int idx = blockIdx.x*256 + threadIdx.x;
    if (idx >= NT*NHh*32) return;
    int d  = idx & 31;
    int h  = (idx >> 5) & 7;
    int bt = idx >> 8;            // b*1024 + t
    int tt = bt & (Tt-1);
    int b  = bt >> 10;
    // inv_freq = 10000^(-d/32)
    float inv = expf(-(float)d * 0.28782313662425575f);   // ln(1e4)/32
    float sn, cs;
    sincosf((float)tt * inv, &sn, &cs);
    size_t bi = (size_t)bt*1536 + h*64 + d;
    float q1 = qkv[bi],        q2 = qkv[bi+32];
    float k1 = qkv[bi+512],    k2 = qkv[bi+544];
    float v1 = qkv[bi+1024],   v2 = qkv[bi+1056];
    int bh = b*NHh + h;
    size_t oi = ((size_t)bh*Tt + tt)*64 + d;
    Q[oi]    = q1*cs - q2*sn;  Q[oi+32] = q1*sn + q2*cs;
    K[oi]    = k1*cs - k2*sn;  K[oi+32] = k1*sn + k2*cs;
    V[oi]    = v1;             V[oi+32] = v2;
}

// ---------------- flash attention (causal, HD=64) ---------------------------
// grid: (qt=16, bh=16), block 256. dynamic smem = 3 * 64*65*4 bytes.
__global__ void attn_kernel(const float* __restrict__ Q,
                            const float* __restrict__ K,
                            const float* __restrict__ V,
                            float* __restrict__ Out) {
    extern __shared__ float sm[];
    float* Qs  = sm;             // 64x65
    float* KPs = sm + 64*65;     // K tile, reused as P tile
    float* Vs  = sm + 2*64*65;
    int qt = blockIdx.x, bh = blockIdx.y;
    int t = threadIdx.x;
    int rg = t >> 4, cg = t & 15;          // 4 rows x 4 cols per thread
    const float* Qb = Q + (size_t)bh*Tt*64;
    const float* Kb = K + (size_t)bh*Tt*64;
    const float* Vb = V + (size_t)bh*Tt*64;
#pragma unroll
    for (int i = 0; i < 4; i++) {
        int idx = t + i*256;
        int r = idx >> 4, c4 = (idx & 15) << 2;
        float4 v4 = *(const float4*)(Qb + (size_t)(qt*64 + r)*64 + c4);
        Qs[r*65+c4+0]=v4.x*0.125f; Qs[r*65+c4+1]=v4.y*0.125f;
        Qs[r*65+c4+2]=v4.z*0.125f; Qs[r*65+c4+3]=v4.w*0.125f;
    }
    float m[4] = {-1e30f,-1e30f,-1e30f,-1e30f};
    float l[4] = {0.f,0.f,0.f,0.f};
    float O[4][4] = {};
    for (int kt = 0; kt <= qt; kt++) {
        __syncthreads();
#pragma unroll
        for (int i = 0; i < 4; i++) {
            int idx = t + i*256;
            int r = idx >> 4, c4 = (idx & 15) << 2;
            float4 kv = *(const float4*)(Kb + (size_t)(kt*64 + r)*64 + c4);
            KPs[r*65+c4+0]=kv.x; KPs[r*65+c4+1]=kv.y; KPs[r*65+c4+2]=kv.z; KPs[r*65+c4+3]=kv.w;
            float4 vv = *(const float4*)(Vb + (size_t)(kt*64 + r)*64 + c4);
            Vs[r*65+c4+0]=vv.x; Vs[r*65+c4+1]=vv.y; Vs[r*65+c4+2]=vv.z; Vs[r*65+c4+3]=vv.w;
        }
        __syncthreads();
        float s[4][4] = {};
#pragma unroll
        for (int kk = 0; kk < 64; kk++) {
            float a[4], b[4];
#pragma unroll
            for (int i = 0; i < 4; i++) a[i] = Qs[(rg*4+i)*65 + kk];
#pragma unroll
            for (int j = 0; j < 4; j++) b[j] = KPs[(cg*4+j)*65 + kk];
#pragma unroll
            for (int i = 0; i < 4; i++)
#pragma unroll
                for (int j = 0; j < 4; j++) s[i][j] += a[i]*b[j];
        }
        if (kt == qt) {
#pragma unroll
            for (int i = 0; i < 4; i++)
#pragma unroll
                for (int j = 0; j < 4; j++)
                    if (cg*4+j > rg*4+i) s[i][j] = -1e30f;
        }
#pragma unroll
        for (int i = 0; i < 4; i++) {
            float rm = fmaxf(fmaxf(s[i][0], s[i][1]), fmaxf(s[i][2], s[i][3]));
            for (int o = 8; o; o >>= 1) rm = fmaxf(rm, __shfl_xor_sync(0xffffffffu, rm, o));
            float nm = fmaxf(m[i], rm);
            float f  = expf(m[i] - nm);
            float rs = 0.f;
#pragma unroll
            for (int j = 0; j < 4; j++) { s[i][j] = expf(s[i][j] - nm); rs += s[i][j]; }
            for (int o = 8; o; o >>= 1) rs += __shfl_xor_sync(0xffffffffu, rs, o);
            l[i] = l[i]*f + rs;
            m[i] = nm;
#pragma unroll
            for (int j = 0; j < 4; j++) O[i][j] *= f;
        }
        __syncthreads();   // done reading KPs as K
#pragma unroll
        for (int i = 0; i < 4; i++)
#pragma unroll
            for (int j = 0; j < 4; j++)
                KPs[(rg*4+i)*65 + cg*4+j] = s[i][j];
        __syncthreads();
#pragma unroll
        for (int jk = 0; jk < 64; jk++) {
            float p[4], v[4];
#pragma unroll
            for (int i = 0; i < 4; i++) p[i] = KPs[(rg*4+i)*65 + jk];
#pragma unroll
            for (int j = 0; j < 4; j++) v[j] = Vs[jk*65 + cg*4+j];
#pragma unroll
            for (int i = 0; i < 4; i++)
#pragma unroll
                for (int j = 0; j < 4; j++) O[i][j] += p[i]*v[j];
        }
    }
    int b = bh >> 3, hh = bh & 7;
#pragma unroll
    for (int i = 0; i < 4; i++) {
        float invl = 1.f / l[i];
        int qrow = qt*64 + rg*4 + i;
#pragma unroll
        for (int j = 0; j < 4; j++)
            Out[((size_t)(b*Tt + qrow))*Dd + hh*64 + cg*4 + j] = O[i][j]*invl;
    }
}

// ---------------- router (logits + top-2 + softmax + scatter) ---------------
__global__ void router_kernel(const float* __restrict__ X,
                              const float* __restrict__ RW,
                              int* __restrict__ cnt,
                              int* __restrict__ tok,
                              float* __restrict__ wt) {
    int gtid = blockIdx.x*blockDim.x + threadIdx.x;
    int warp = gtid >> 5, lane = gtid & 31;
    if (warp >= NT) return;
    const float* xr = X + (size_t)warp*Dd;
    float lg[Ee];
#pragma unroll
    for (int e = 0; e < Ee; e++) {
        const float* w = RW + (size_t)e*Dd;
        float s = 0.f;
        for (int j = lane; j < Dd; j += 32) s += xr[j]*w[j];
        for (int o = 16; o; o >>= 1) s += __shfl_xor_sync(0xffffffffu, s, o);
        lg[e] = s;
    }
    if (lane == 0) {
        int i0 = 0; float v0 = lg[0];
#pragma unroll
        for (int e = 1; e < Ee; e++) if (lg[e] > v0) { v0 = lg[e]; i0 = e; }
        int i1 = -1; float v1 = -3.4e38f;
#pragma unroll
        for (int e = 0; e < Ee; e++) if (e != i0 && lg[e] > v1) { v1 = lg[e]; i1 = e; }
        float e1 = expf(v1 - v0);
        float w0 = 1.f/(1.f + e1), w1 = e1/(1.f + e1);
        int p0 = atomicAdd(&cnt[i0], 1);
        tok[i0*NT + p0] = warp*2;     wt[i0*NT + p0] = w0;
        int p1 = atomicAdd(&cnt[i1], 1);
        tok[i1*NT + p1] = warp*2 + 1; wt[i1*NT + p1] = w1;
    }
}

// ---------------- fused FFN up: h = silu(X@W1^T) * (X@W3^T) -----------------
template<bool GROUPED>
__global__ void ffn_up_kernel(const float* __restrict__ X,
                              const float* __restrict__ W1,
                              const float* __restrict__ W3,
                              float* __restrict__ Hbuf,
                              const int* __restrict__ tok,
                              const int* __restrict__ cnt) {
    int e = GROUPED ? blockIdx.z : 0;
    int n = GROUPED ? cnt[e] : NT;
    int rb = blockIdx.y * 64;
    if (rb >= n) return;
    __shared__ float As[64][17], B1s[64][17], B3s[64][17];
    int t = threadIdx.x, tx = t & 15, ty = t >> 4;
    int cb = blockIdx.x * 64;
    int lr = t >> 2, lk = (t & 3) << 2;
    int ar = rb + lr; if (ar > n-1) ar = n-1;
    int xrow = GROUPED ? (tok[e*NT + ar] >> 1) : ar;
    const float* xr = X  + (size_t)xrow*Dd;
    const float* w1 = W1 + (size_t)e*Hh*Dd + (size_t)(cb + lr)*Dd;
    const float* w3 = W3 + (size_t)e*Hh*Dd + (size_t)(cb + lr)*Dd;
    float a1[4][4] = {}, a3[4][4] = {};
    for (int k0 = 0; k0 < Dd; k0 += 16) {
        float4 xv  = *(const float4*)(xr + k0 + lk);
        float4 w1v = *(const float4*)(w1 + k0 + lk);
        float4 w3v = *(const float4*)(w3 + k0 + lk);
        As [lr][lk+0]=xv.x;  As [lr][lk+1]=xv.y;  As [lr][lk+2]=xv.z;  As [lr][lk+3]=xv.w;
        B1s[lr][lk+0]=w1v.x; B1s[lr][lk+1]=w1v.y; B1s[lr][lk+2]=w1v.z; B1s[lr][lk+3]=w1v.w;
        B3s[lr][lk+0]=w3v.x; B3s[lr][lk+1]=w3v.y; B3s[lr][lk+2]=w3v.z; B3s[lr][lk+3]=w3v.w;
        __syncthreads();
#pragma unroll
        for (int kk = 0; kk < 16; kk++) {
            float a[4], b1[4], b3[4];
#pragma unroll
            for (int i = 0; i < 4; i++) a[i]  = As [ty*4+i][kk];
#pragma unroll
            for (int j = 0; j < 4; j++) { b1[j] = B1s[tx*4+j][kk]; b3[j] = B3s[tx*4+j][kk]; }
#pragma unroll
            for (int i = 0; i < 4; i++)
#pragma unroll
                for (int j = 0; j < 4; j++) { a1[i][j] += a[i]*b1[j]; a3[i][j] += a[i]*b3[j]; }
        }
        __syncthreads();
    }
#pragma unroll
    for (int i = 0; i < 4; i++) {
        int r = rb + ty*4 + i;
        if (r < n) {
#pragma unroll
            for (int j = 0; j < 4; j++) {
                float g = a1[i][j], u = a3[i][j];
                float hv = g / (1.f + expf(-g)) * u;
                Hbuf[((size_t)e*NT + r)*Hh + cb + tx*4 + j] = hv;
            }
        }
    }
}

// ---------------- FFN down: out = Hbuf @ W2^T (scatter or residual) ---------
template<bool GROUPED>
__global__ void ffn_down_kernel(const float* __restrict__ Hbuf,
                                const float* __restrict__ W2,
                                float* __restrict__ Out,      // dense: g_h ; grouped: yslot
                                const int* __restrict__ tok,
                                const float* __restrict__ wt,
                                const int* __restrict__ cnt) {
    int e = GROUPED ? blockIdx.z : 0;
    int n = GROUPED ? cnt[e] : NT;
    int rb = blockIdx.y * 64;
    if (rb >= n) return;
    __shared__ float As[64][17], Bs[64][17];
    int t = threadIdx.x, tx = t & 15, ty = t >> 4;
    int cb = blockIdx.x * 64;
    int lr = t >> 2, lk = (t & 3) << 2;
    int ar = rb + lr; if (ar > n-1) ar = n-1;
    const float* arow = Hbuf + ((size_t)e*NT + ar)*Hh;
    const float* brow = W2 + (size_t)e*Dd*Hh + (size_t)(cb + lr)*Hh;
    float acc[4][4] = {};
    for (int k0 = 0; k0 < Hh; k0 += 16) {
        float4 av = *(const float4*)(arow + k0 + lk);
        float4 bv = *(const float4*)(brow + k0 + lk);
        As[lr][lk+0]=av.x; As[lr][lk+1]=av.y; As[lr][lk+2]=av.z; As[lr][lk+3]=av.w;
        Bs[lr][lk+0]=bv.x; Bs[lr][lk+1]=bv.y; Bs[lr][lk+2]=bv.z; Bs[lr][lk+3]=bv.w;
        __syncthreads();
#pragma unroll
        for (int kk = 0; kk < 16; kk++) {
            float a[4], b[4];
#pragma unroll
            for (int i = 0; i < 4; i++) a[i] = As[ty*4+i][kk];
#pragma unroll
            for (int j = 0; j < 4; j++) b[j] = Bs[tx*4+j][kk];
#pragma unroll
            for (int i = 0; i < 4; i++)
#pragma unroll
                for (int j = 0; j < 4; j++) acc[i][j] += a[i]*b[j];
        }
        __syncthreads();
    }
#pragma unroll
    for (int i = 0; i < 4; i++) {
        int r = rb + ty*4 + i;
        if (r < n) {
            if (GROUPED) {
                int pk = tok[e*NT + r];
                float w = wt[e*NT + r];
#pragma unroll
                for (int j = 0; j < 4; j++)
                    Out[(size_t)pk*Dd + cb + tx*4 + j] = w * acc[i][j];
            } else {
#pragma unroll
                for (int j = 0; j < 4; j++)
                    Out[(size_t)r*Dd + cb + tx*4 + j] += acc[i][j];
            }
        }
    }
}

// ---------------- combine: h += yslot[2t] + yslot[2t+1] ---------------------
__global__ void combine_kernel(float* __restrict__ h, const float* __restrict__ ys) {
    int idx = blockIdx.x*256 + threadIdx.x;
    if (idx >= NT*Dd) return;
    int tk = idx / Dd, d = idx - tk*Dd;
    h[idx] += ys[(size_t)(2*tk)*Dd + d] + ys[(size_t)(2*tk+1)*Dd + d];
}

// ---------------- host orchestration ----------------------------------------
extern "C" void kernel_launch(void* const* d_in, const int* in_sizes, int n_in,
                              void* d_out, int out_size) {
    (void)in_sizes; (void)n_in; (void)out_size;
    const float* x        = (const float*)d_in[0];
    const float* qkv_w    = (const float*)d_in[1];
    const float* out_w    = (const float*)d_in[2];
    const float* norm1_w  = (const float*)d_in[3];
    const float* norm2_w  = (const float*)d_in[4];
    const float* router_w = (const float*)d_in[5];
    const float* moe_w1   = (const float*)d_in[6];
    const float* moe_w2   = (const float*)d_in[7];
    const float* moe_w3   = (const float*)d_in[8];
    const float* f_w1     = (const float*)d_in[9];
    const float* f_w2     = (const float*)d_in[10];
    const float* f_w3     = (const float*)d_in[11];
    const float* norm_f   = (const float*)d_in[12];
    float* out = (float*)d_out;

    float *h, *xn, *qkv, *q, *k, *v, *attn, *hbuf, *yslot, *wt;
    int *cnt, *tok;
    cudaGetSymbolAddress((void**)&h,    g_h);
    cudaGetSymbolAddress((void**)&xn,   g_xn);
    cudaGetSymbolAddress((void**)&qkv,  g_qkv);
    cudaGetSymbolAddress((void**)&q,    g_q);
    cudaGetSymbolAddress((void**)&k,    g_k);
    cudaGetSymbolAddress((void**)&v,    g_v);
    cudaGetSymbolAddress((void**)&attn, g_attn);
    cudaGetSymbolAddress((void**)&hbuf, g_hbuf);
    cudaGetSymbolAddress((void**)&yslot,g_yslot);
    cudaGetSymbolAddress((void**)&cnt,  g_cnt);
    cudaGetSymbolAddress((void**)&tok,  g_tok);
    cudaGetSymbolAddress((void**)&wt,   g_wt);

    const int attn_smem = 3 * 64 * 65 * sizeof(float);   // 49,920 B
    cudaFuncSetAttribute(attn_kernel, cudaFuncAttributeMaxDynamicSharedMemorySize, attn_smem);

    cudaMemcpyAsync(h, x, (size_t)NT*Dd*sizeof(float), cudaMemcpyDeviceToDevice, 0);

    for (int l = 0; l < Ll; l++) {
        rmsnorm_kernel<<<NT, 256>>>(h, norm1_w + (size_t)l*Dd, xn);
        gemm_nt_kernel<<<dim3(1536/64, NT/64), 256>>>(
            xn, qkv_w + (size_t)l*1536*Dd, qkv, nullptr, 1536, Dd);
        split_rope_kernel<<<(NT*NHh*32 + 255)/256, 256>>>(qkv, q, k, v);
        attn_kernel<<<dim3(Tt/64, Bz*NHh), 256, attn_smem>>>(q, k, v, attn);
        gemm_nt_kernel<<<dim3(Dd/64, NT/64), 256>>>(
            attn, out_w + (size_t)l*Dd*Dd, h, h, Dd, Dd);
        rmsnorm_kernel<<<NT, 256>>>(h, norm2_w + (size_t)l*Dd, xn);

        if (l == 0 || l == 2) {                 // MoE layers
            int m = l / 2;
            cudaMemsetAsync(cnt, 0, Ee*sizeof(int), 0);
            router_kernel<<<(NT*32 + 127)/128, 128>>>(
                xn, router_w + (size_t)m*Ee*Dd, cnt, tok, wt);
            ffn_up_kernel<true><<<dim3(Hh/64, NT/64, Ee), 256>>>(
                xn, moe_w1 + (size_t)m*Ee*Hh*Dd, moe_w3 + (size_t)m*Ee*Hh*Dd,
                hbuf, tok, cnt);
            ffn_down_kernel<true><<<dim3(Dd/64, NT/64, Ee), 256>>>(
                hbuf, moe_w2 + (size_t)m*Ee*Dd*Hh, yslot, tok, wt, cnt);
            combine_kernel<<<(NT*Dd + 255)/256, 256>>>(h, yslot);
        } else {                                // dense SwiGLU layers
            int m = (l == 1) ? 0 : 1;
            ffn_up_kernel<false><<<dim3(Hh/64, NT/64, 1), 256>>>(
                xn, f_w1 + (size_t)m*Hh*Dd, f_w3 + (size_t)m*Hh*Dd,
                hbuf, nullptr, nullptr);
            ffn_down_kernel<false><<<dim3(Dd/64, NT/64, 1), 256>>>(
                hbuf, f_w2 + (size_t)m*Dd*Hh, h, nullptr, nullptr, nullptr);
        }
    }
    rmsnorm_kernel<<<NT, 256>>>(h, norm_f, out);
}